// round 3
// baseline (speedup 1.0000x reference)
#include <cuda_runtime.h>
#include <cuda_bf16.h>
#include <math.h>

// Problem constants (fixed by the dataset)
#define BATCH 4
#define NVERT 6890
#define NFACE 27552          // 2 * 13776
#define IMGSZ 128
#define UVH 256
#define UVW 256
#define NTILE 8              // 8x8 tiles of 16x16 pixels
#define FCHUNK 256

// Per-face record: 4 float4
//  q0 = (x0, y0, x1, y1)
//  q1 = (x2, y2, z0, z1)
//  q2 = (z2, minx, maxx, miny)
//  q3 = (maxy, area, 0, 0)
__device__ float4 g_face[BATCH * NFACE * 4];

// ---------------------------------------------------------------------------
// Kernel 1: project vertices per (batch, face), compute bbox + signed area
// ---------------------------------------------------------------------------
__global__ void setup_faces_kernel(const float* __restrict__ cam,
                                   const float* __restrict__ verts,
                                   const int*   __restrict__ faces)
{
    int idx = blockIdx.x * blockDim.x + threadIdx.x;
    if (idx >= BATCH * NFACE) return;
    int b = idx / NFACE;
    int f = idx - b * NFACE;

    float c0 = cam[b * 3 + 0];
    float c1 = cam[b * 3 + 1];
    float c2 = cam[b * 3 + 2];
    float tz = 500.0f / (64.0f * c0);

    float x[3], y[3], z[3];
#pragma unroll
    for (int k = 0; k < 3; k++) {
        int vid = faces[f * 3 + k];
        const float* v = verts + ((long)b * NVERT + vid) * 3;
        x[k] = __fmul_rn(c0, __fadd_rn(v[0], c1));
        y[k] = __fmul_rn(c0, __fadd_rn(v[1], c2));
        z[k] = v[2] + tz;
    }
    float minx = fminf(x[0], fminf(x[1], x[2])) - 1e-6f;
    float maxx = fmaxf(x[0], fmaxf(x[1], x[2])) + 1e-6f;
    float miny = fminf(y[0], fminf(y[1], y[2])) - 1e-6f;
    float maxy = fmaxf(y[0], fmaxf(y[1], y[2])) + 1e-6f;
    // signed area (cull-only; exact per-pixel value recomputed in raster)
    float area = (x[1] - x[0]) * (y[2] - y[0]) - (x[2] - x[0]) * (y[1] - y[0]);

    float4* o = g_face + (long)idx * 4;
    o[0] = make_float4(x[0], y[0], x[1], y[1]);
    o[1] = make_float4(x[2], y[2], z[0], z[1]);
    o[2] = make_float4(z[2], minx, maxx, miny);
    o[3] = make_float4(maxy, area, 0.0f, 0.0f);
}

// Reference-faithful edge functions: no FMA contraction.
__device__ __forceinline__ void edge_fns(float x0, float y0, float x1, float y1,
                                         float x2, float y2, float px, float py,
                                         float& w0, float& w1, float& w2)
{
    w0 = __fsub_rn(__fmul_rn(__fsub_rn(x2, x1), __fsub_rn(py, y1)),
                   __fmul_rn(__fsub_rn(y2, y1), __fsub_rn(px, x1)));
    w1 = __fsub_rn(__fmul_rn(__fsub_rn(x0, x2), __fsub_rn(py, y2)),
                   __fmul_rn(__fsub_rn(y0, y2), __fsub_rn(px, x2)));
    w2 = __fsub_rn(__fmul_rn(__fsub_rn(x1, x0), __fsub_rn(py, y0)),
                   __fmul_rn(__fsub_rn(y1, y0), __fsub_rn(px, x0)));
}

// ---------------------------------------------------------------------------
// Kernel 2: per-tile rasterize (z-min with first-index tie-break) + shade
// One block = one 16x16 pixel tile of one batch. 256 threads, 1 pixel each.
// ---------------------------------------------------------------------------
__global__ void __launch_bounds__(256)
raster_shade_kernel(const float* __restrict__ uv_imgs,
                    const float* __restrict__ sampler,
                    float* __restrict__ out)
{
    int blk  = blockIdx.x;               // 0 .. BATCH*64-1
    int b    = blk >> 6;
    int tile = blk & 63;
    int tx0  = (tile & 7) * 16;
    int ty0  = (tile >> 3) * 16;
    int tid  = threadIdx.x;
    int ix   = tx0 + (tid & 15);
    int iy   = ty0 + (tid >> 4);

    // pixel centers (exact in fp32: (2i+1)/128 is exact)
    float px = (2.0f * ix + 1.0f) / 128.0f - 1.0f;
    float py = 1.0f - (2.0f * iy + 1.0f) / 128.0f;

    // tile NDC bounds (pixel centers)
    float xlo = (2.0f * tx0 + 1.0f) / 128.0f - 1.0f;
    float xhi = (2.0f * (tx0 + 15) + 1.0f) / 128.0f - 1.0f;
    float yhi = 1.0f - (2.0f * ty0 + 1.0f) / 128.0f;
    float ylo = 1.0f - (2.0f * (ty0 + 15) + 1.0f) / 128.0f;

    __shared__ float sx0[FCHUNK], sy0[FCHUNK], sx1[FCHUNK], sy1[FCHUNK];
    __shared__ float sx2[FCHUNK], sy2[FCHUNK];
    __shared__ float sz0[FCHUNK], sz1[FCHUNK], sz2[FCHUNK];
    __shared__ int   sfid[FCHUNK];
    __shared__ int   swcnt[8];

    float zbest = 1e10f;
    int   fbest = -1;

    const float4* gf = g_face + (long)b * NFACE * 4;
    int wid  = tid >> 5;
    int lane = tid & 31;

    for (int base = 0; base < NFACE; base += FCHUNK) {
        int f = base + tid;
        bool keep = false;
        float4 q0, q1, q2, q3;
        if (f < NFACE) {
            const float4* r = gf + (long)f * 4;
            q0 = r[0]; q1 = r[1]; q2 = r[2]; q3 = r[3];
            // q2=(z2,minx,maxx,miny) q3=(maxy,area,..)
            keep = (q2.z >= xlo) && (q2.y <= xhi) &&
                   (q3.x >= ylo) && (q2.w <= yhi) &&
                   (q3.y > -1e-3f);
        }
        unsigned m = __ballot_sync(0xffffffffu, keep);
        if (lane == 0) swcnt[wid] = __popc(m);
        __syncthreads();
        int offset = 0, total = 0;
#pragma unroll
        for (int w = 0; w < 8; w++) {
            int c = swcnt[w];
            total += c;
            if (w < wid) offset += c;
        }
        if (keep) {
            int pos = offset + __popc(m & ((1u << lane) - 1u));
            sx0[pos] = q0.x; sy0[pos] = q0.y;
            sx1[pos] = q0.z; sy1[pos] = q0.w;
            sx2[pos] = q1.x; sy2[pos] = q1.y;
            sz0[pos] = q1.z; sz1[pos] = q1.w;
            sz2[pos] = q2.x; sfid[pos] = f;
        }
        __syncthreads();

        for (int j = 0; j < total; j++) {
            float w0, w1, w2;
            edge_fns(sx0[j], sy0[j], sx1[j], sy1[j], sx2[j], sy2[j], px, py,
                     w0, w1, w2);
            float area = w0 + w1 + w2;
            if ((w0 >= 0.0f) && (w1 >= 0.0f) && (w2 >= 0.0f) && (area > 0.0f)) {
                float b0 = w0 / area;
                float b1 = w1 / area;
                float b2 = w2 / area;
                float invz = b0 / sz0[j] + b1 / sz1[j] + b2 / sz2[j];
                float zp = (invz == 0.0f) ? 1.0f : 1.0f / invz;
                if (zp > 0.1f && zp < 25.0f && zp < zbest) {
                    zbest = zp;
                    fbest = sfid[j];
                }
            }
        }
        __syncthreads();
    }

    // ---- shading ----
    float col0 = 0.0f, col1 = 0.0f, col2 = 0.0f;
    if (fbest >= 0) {
        const float4* r = gf + (long)fbest * 4;
        float4 q0 = r[0], q1 = r[1];
        float w0, w1, w2;
        edge_fns(q0.x, q0.y, q0.z, q0.w, q1.x, q1.y, px, py, w0, w1, w2);
        float area = w0 + w1 + w2;
        float s = (area == 0.0f) ? 1.0f : area;
        float b0 = w0 / s;
        float b1 = w1 / s;
        int t0 = min(max((int)floorf(b0 * 3.0f), 0), 2);
        int t1 = min(max((int)floorf(b1 * 3.0f), 0), 2);

        int sidx = (fbest * 9 + t0 * 3 + t1) * 2;
        float gx = sampler[sidx];
        float gy = sampler[sidx + 1];
        float xf = (gx + 1.0f) * 128.0f - 0.5f;   // W*0.5 = 128
        float yf = (gy + 1.0f) * 128.0f - 0.5f;
        float xof = floorf(xf), yof = floorf(yf);
        float wx = xf - xof, wy = yf - yof;
        int xi0 = (int)xof, yi0 = (int)yof;

        const float* img = uv_imgs + (long)b * 3 * UVH * UVW;
        float ws[4] = { (1.0f - wx) * (1.0f - wy), wx * (1.0f - wy),
                        (1.0f - wx) * wy,          wx * wy };
        int xs4[4] = { xi0, xi0 + 1, xi0,     xi0 + 1 };
        int ys4[4] = { yi0, yi0,     yi0 + 1, yi0 + 1 };
#pragma unroll
        for (int t = 0; t < 4; t++) {
            int xi = xs4[t], yi = ys4[t];
            bool valid = (xi >= 0) && (xi < UVW) && (yi >= 0) && (yi < UVH);
            float w = valid ? ws[t] : 0.0f;
            int xc = min(max(xi, 0), UVW - 1);
            int yc = min(max(yi, 0), UVH - 1);
            int p = yc * UVW + xc;
            col0 += img[p] * w;
            col1 += img[UVH * UVW + p] * w;
            col2 += img[2 * UVH * UVW + p] * w;
        }
    }
    int pofs = iy * IMGSZ + ix;
    out[((long)b * 3 + 0) * IMGSZ * IMGSZ + pofs] = col0;
    out[((long)b * 3 + 1) * IMGSZ * IMGSZ + pofs] = col1;
    out[((long)b * 3 + 2) * IMGSZ * IMGSZ + pofs] = col2;
}

// ---------------------------------------------------------------------------
// kernel_launch
//   d_in[0] cam            (B,3)          float32
//   d_in[1] vertices       (B,NV,3)       float32
//   d_in[2] uv_imgs        (B,3,256,256)  float32
//   d_in[3] img2uv_sampler (F,9,2)        float32
//   d_in[4] faces          (F,3)          int32
//   d_out   images         (B,3,128,128)  float32
// ---------------------------------------------------------------------------
extern "C" void kernel_launch(void* const* d_in, const int* in_sizes, int n_in,
                              void* d_out, int out_size)
{
    const float* cam     = (const float*)d_in[0];
    const float* verts   = (const float*)d_in[1];
    const float* uv_imgs = (const float*)d_in[2];
    const float* sampler = (const float*)d_in[3];
    const int*   faces   = (const int*)d_in[4];
    float*       out     = (float*)d_out;

    int nsetup = BATCH * NFACE;
    setup_faces_kernel<<<(nsetup + 255) / 256, 256>>>(cam, verts, faces);
    raster_shade_kernel<<<BATCH * 64, 256>>>(uv_imgs, sampler, out);
}

// round 4
// speedup vs baseline: 18.7296x; 18.7296x over previous
#include <cuda_runtime.h>
#include <cuda_bf16.h>
#include <math.h>

// Problem constants (fixed by the dataset)
#define BATCH 4
#define NVERT 6890
#define NFACE 27552          // 2 * 13776
#define IMGSZ 128
#define UVH 256
#define UVW 256

// Per-face record: 4 float4
//  q0 = (x0, y0, x1, y1)
//  q1 = (x2, y2, z0, z1)
//  q2 = (z2, minx, maxx, miny)
//  q3 = (maxy, area, 0, 0)
__device__ float4 g_face[BATCH * NFACE * 4];
// Packed z-buffer: (float_bits(zp) << 32) | face_id.  Min == reference winner.
__device__ unsigned long long g_zbuf[BATCH * IMGSZ * IMGSZ];

// ---------------------------------------------------------------------------
// Kernel 0: init z-buffer
// ---------------------------------------------------------------------------
__global__ void init_zbuf_kernel()
{
    int i = blockIdx.x * blockDim.x + threadIdx.x;
    if (i < BATCH * IMGSZ * IMGSZ) g_zbuf[i] = 0xFFFFFFFFFFFFFFFFULL;
}

// ---------------------------------------------------------------------------
// Kernel 1: project vertices per (batch, face), compute bbox + signed area
// ---------------------------------------------------------------------------
__global__ void setup_faces_kernel(const float* __restrict__ cam,
                                   const float* __restrict__ verts,
                                   const int*   __restrict__ faces)
{
    int idx = blockIdx.x * blockDim.x + threadIdx.x;
    if (idx >= BATCH * NFACE) return;
    int b = idx / NFACE;
    int f = idx - b * NFACE;

    float c0 = cam[b * 3 + 0];
    float c1 = cam[b * 3 + 1];
    float c2 = cam[b * 3 + 2];
    float tz = 500.0f / (64.0f * c0);

    float x[3], y[3], z[3];
#pragma unroll
    for (int k = 0; k < 3; k++) {
        int vid = faces[f * 3 + k];
        const float* v = verts + ((long)b * NVERT + vid) * 3;
        x[k] = __fmul_rn(c0, __fadd_rn(v[0], c1));
        y[k] = __fmul_rn(c0, __fadd_rn(v[1], c2));
        z[k] = v[2] + tz;
    }
    float minx = fminf(x[0], fminf(x[1], x[2])) - 1e-6f;
    float maxx = fmaxf(x[0], fmaxf(x[1], x[2])) + 1e-6f;
    float miny = fminf(y[0], fminf(y[1], y[2])) - 1e-6f;
    float maxy = fmaxf(y[0], fmaxf(y[1], y[2])) + 1e-6f;
    // signed area (cull-only; exact per-pixel value recomputed in raster)
    float area = (x[1] - x[0]) * (y[2] - y[0]) - (x[2] - x[0]) * (y[1] - y[0]);

    float4* o = g_face + (long)idx * 4;
    o[0] = make_float4(x[0], y[0], x[1], y[1]);
    o[1] = make_float4(x[2], y[2], z[0], z[1]);
    o[2] = make_float4(z[2], minx, maxx, miny);
    o[3] = make_float4(maxy, area, 0.0f, 0.0f);
}

// ---------------------------------------------------------------------------
// Kernel 2: face-parallel scanline rasterizer.
// One warp per (batch, face); lanes stride rows of the face bbox.
// Exact reference edge functions decide insideness; depth screened with a
// fast approximation, exact 7-divide reference chain only for possible
// winners; 64-bit packed atomicMin = min depth, lowest face id on ties.
// ---------------------------------------------------------------------------
__global__ void __launch_bounds__(256)
raster_kernel()
{
    int gwarp = (blockIdx.x * blockDim.x + threadIdx.x) >> 5;
    int lane  = threadIdx.x & 31;
    if (gwarp >= BATCH * NFACE) return;
    int b = gwarp / NFACE;
    int f = gwarp - b * NFACE;

    const float4* r = g_face + (long)(b * NFACE + f) * 4;
    float4 q0 = r[0], q1 = r[1], q2 = r[2], q3 = r[3];
    float x0 = q0.x, y0 = q0.y, x1 = q0.z, y1 = q0.w;
    float x2 = q1.x, y2 = q1.y, z0 = q1.z, z1 = q1.w;
    float z2 = q2.x, minx = q2.y, maxx = q2.z, miny = q2.w;
    float maxy = q3.x, farea = q3.y;

    if (farea <= -1e-3f) return;     // reversed-winding faces can never pass area>0
    if (maxx < -1.0f || minx > 1.0f || maxy < -1.0f || miny > 1.0f) return;

    // Edge deltas: exact subexpressions of the reference formula.
    float dx21 = __fsub_rn(x2, x1), dy21 = __fsub_rn(y2, y1);
    float dx02 = __fsub_rn(x0, x2), dy02 = __fsub_rn(y0, y2);
    float dx10 = __fsub_rn(x1, x0), dy10 = __fsub_rn(y1, y0);

    // Fast reciprocals for the depth screen only.
    float rz0 = __fdividef(1.0f, z0);
    float rz1 = __fdividef(1.0f, z1);
    float rz2 = __fdividef(1.0f, z2);

    // Pixel-space bbox, expanded by 1 px for safety.
    int ixlo = max(0,   (int)floorf((minx + 1.0f) * 64.0f - 0.5f) - 1);
    int ixhi = min(127, (int)ceilf ((maxx + 1.0f) * 64.0f - 0.5f) + 1);
    int iylo = max(0,   (int)floorf((1.0f - maxy) * 64.0f - 0.5f) - 1);
    int iyhi = min(127, (int)ceilf ((1.0f - miny) * 64.0f - 0.5f) + 1);
    if (ixlo > ixhi || iylo > iyhi) return;

    unsigned long long* zb = g_zbuf + b * (IMGSZ * IMGSZ);

    for (int iy = iylo + lane; iy <= iyhi; iy += 32) {
        float py = 0.9921875f - iy * 0.015625f;   // exact pixel-center y
        // Per-row edge constants (exact).
        float t0 = __fmul_rn(dx21, __fsub_rn(py, y1));
        float t1 = __fmul_rn(dx02, __fsub_rn(py, y2));
        float t2 = __fmul_rn(dx10, __fsub_rn(py, y0));

        // Conservative x-interval: w_e(px) = t_e - dy_e*(px - xa_e) >= 0.
        float xlo = -2.0f, xhi = 2.0f;
        bool empty = false;
        {
            float dys[3] = { dy21, dy02, dy10 };
            float ts [3] = { t0,   t1,   t2   };
            float xas[3] = { x1,   x2,   x0   };
#pragma unroll
            for (int e = 0; e < 3; e++) {
                float dy = dys[e], t = ts[e], xa = xas[e];
                float ady = fabsf(dy);
                if (ady > 1e-6f) {
                    float root  = xa + t / dy;
                    float slack = __fdividef(4e-6f, ady) + 1e-6f;
                    if (dy > 0.0f) xhi = fminf(xhi, root + slack);
                    else           xlo = fmaxf(xlo, root - slack);
                } else if (t < -1e-5f) {
                    empty = true;   // nearly-horizontal edge, certainly negative
                }
            }
        }
        if (empty || xlo > xhi) continue;
        int rxlo = max(ixlo, (int)floorf((xlo + 1.0f) * 64.0f - 0.5f));
        int rxhi = min(ixhi, (int)ceilf ((xhi + 1.0f) * 64.0f - 0.5f));

        for (int ix = rxlo; ix <= rxhi; ix++) {
            float px = fmaf((float)ix, 0.015625f, -0.9921875f);  // exact
            // Exact reference edge functions (no FMA contraction).
            float w0 = __fsub_rn(t0, __fmul_rn(dy21, __fsub_rn(px, x1)));
            float w1 = __fsub_rn(t1, __fmul_rn(dy02, __fsub_rn(px, x2)));
            float w2 = __fsub_rn(t2, __fmul_rn(dy10, __fsub_rn(px, x0)));
            float area = __fadd_rn(__fadd_rn(w0, w1), w2);
            if (!(w0 >= 0.0f && w1 >= 0.0f && w2 >= 0.0f && area > 0.0f)) continue;

            // Fast depth screen (rel err <= ~2e-6; margin 2e-5).
            float invzn = fmaf(w0, rz0, fmaf(w1, rz1, w2 * rz2));
            float zscr  = __fdividef(area, invzn);
            int   pix   = iy * IMGSZ + ix;
            unsigned long long cur = zb[pix];
            float zbest = __uint_as_float((unsigned)(cur >> 32)); // NaN initially
            if (zscr > zbest * 1.00002f) continue;   // certainly loses (false on NaN)
            if (zscr < 0.0995f)          continue;   // certainly < NEAR
            if (zscr > 25.003f)          continue;   // certainly > FAR

            // Exact reference depth chain (IEEE, same order/association).
            float b0 = __fdiv_rn(w0, area);
            float b1 = __fdiv_rn(w1, area);
            float b2 = __fdiv_rn(w2, area);
            float invz = __fadd_rn(__fadd_rn(__fdiv_rn(b0, z0),
                                             __fdiv_rn(b1, z1)),
                                   __fdiv_rn(b2, z2));
            float zp = (invz == 0.0f) ? 1.0f : __fdiv_rn(1.0f, invz);
            if (zp > 0.1f && zp < 25.0f) {
                unsigned long long pk =
                    ((unsigned long long)__float_as_uint(zp) << 32) | (unsigned)f;
                atomicMin(&zb[pix], pk);
            }
        }
    }
}

// ---------------------------------------------------------------------------
// Kernel 3: per-pixel shading from the packed z-buffer.
// ---------------------------------------------------------------------------
__global__ void __launch_bounds__(256)
shade_kernel(const float* __restrict__ uv_imgs,
             const float* __restrict__ sampler,
             float* __restrict__ out)
{
    int gid = blockIdx.x * blockDim.x + threadIdx.x;   // 0 .. 65535
    if (gid >= BATCH * IMGSZ * IMGSZ) return;
    int b    = gid >> 14;
    int pofs = gid & 16383;
    int iy   = pofs >> 7;
    int ix   = pofs & 127;

    unsigned long long pk = g_zbuf[gid];
    unsigned zbits = (unsigned)(pk >> 32);

    float col0 = 0.0f, col1 = 0.0f, col2 = 0.0f;
    if (zbits != 0xFFFFFFFFu) {
        int fbest = (int)(unsigned)(pk & 0xFFFFFFFFu);
        float px = fmaf((float)ix, 0.015625f, -0.9921875f);
        float py = 0.9921875f - iy * 0.015625f;

        const float4* r = g_face + (long)(b * NFACE + fbest) * 4;
        float4 q0 = r[0], q1 = r[1];
        float x0 = q0.x, y0 = q0.y, x1 = q0.z, y1 = q0.w;
        float x2 = q1.x, y2 = q1.y;
        // Exact reference edge functions.
        float w0 = __fsub_rn(__fmul_rn(__fsub_rn(x2, x1), __fsub_rn(py, y1)),
                             __fmul_rn(__fsub_rn(y2, y1), __fsub_rn(px, x1)));
        float w1 = __fsub_rn(__fmul_rn(__fsub_rn(x0, x2), __fsub_rn(py, y2)),
                             __fmul_rn(__fsub_rn(y0, y2), __fsub_rn(px, x2)));
        float w2 = __fsub_rn(__fmul_rn(__fsub_rn(x1, x0), __fsub_rn(py, y0)),
                             __fmul_rn(__fsub_rn(y1, y0), __fsub_rn(px, x0)));
        float area = __fadd_rn(__fadd_rn(w0, w1), w2);
        float s  = (area == 0.0f) ? 1.0f : area;
        float b0 = __fdiv_rn(w0, s);
        float b1 = __fdiv_rn(w1, s);
        int t0 = min(max((int)floorf(b0 * 3.0f), 0), 2);
        int t1 = min(max((int)floorf(b1 * 3.0f), 0), 2);

        int sidx = (fbest * 9 + t0 * 3 + t1) * 2;
        float gx = sampler[sidx];
        float gy = sampler[sidx + 1];
        float xf = (gx + 1.0f) * 128.0f - 0.5f;   // W*0.5 = 128
        float yf = (gy + 1.0f) * 128.0f - 0.5f;
        float xof = floorf(xf), yof = floorf(yf);
        float wx = xf - xof, wy = yf - yof;
        int xi0 = (int)xof, yi0 = (int)yof;

        const float* img = uv_imgs + (long)b * 3 * UVH * UVW;
        float ws[4] = { (1.0f - wx) * (1.0f - wy), wx * (1.0f - wy),
                        (1.0f - wx) * wy,          wx * wy };
        int xs4[4] = { xi0, xi0 + 1, xi0,     xi0 + 1 };
        int ys4[4] = { yi0, yi0,     yi0 + 1, yi0 + 1 };
#pragma unroll
        for (int t = 0; t < 4; t++) {
            int xi = xs4[t], yi = ys4[t];
            bool valid = (xi >= 0) && (xi < UVW) && (yi >= 0) && (yi < UVH);
            float w = valid ? ws[t] : 0.0f;
            int xc = min(max(xi, 0), UVW - 1);
            int yc = min(max(yi, 0), UVH - 1);
            int p = yc * UVW + xc;
            col0 += img[p] * w;
            col1 += img[UVH * UVW + p] * w;
            col2 += img[2 * UVH * UVW + p] * w;
        }
    }
    int po = iy * IMGSZ + ix;
    out[((long)b * 3 + 0) * IMGSZ * IMGSZ + po] = col0;
    out[((long)b * 3 + 1) * IMGSZ * IMGSZ + po] = col1;
    out[((long)b * 3 + 2) * IMGSZ * IMGSZ + po] = col2;
}

// ---------------------------------------------------------------------------
// kernel_launch
//   d_in[0] cam            (B,3)          float32
//   d_in[1] vertices       (B,NV,3)       float32
//   d_in[2] uv_imgs        (B,3,256,256)  float32
//   d_in[3] img2uv_sampler (F,9,2)        float32
//   d_in[4] faces          (F,3)          int32
//   d_out   images         (B,3,128,128)  float32
// ---------------------------------------------------------------------------
extern "C" void kernel_launch(void* const* d_in, const int* in_sizes, int n_in,
                              void* d_out, int out_size)
{
    const float* cam     = (const float*)d_in[0];
    const float* verts   = (const float*)d_in[1];
    const float* uv_imgs = (const float*)d_in[2];
    const float* sampler = (const float*)d_in[3];
    const int*   faces   = (const int*)d_in[4];
    float*       out     = (float*)d_out;

    init_zbuf_kernel<<<(BATCH * IMGSZ * IMGSZ + 255) / 256, 256>>>();
    int nsetup = BATCH * NFACE;
    setup_faces_kernel<<<(nsetup + 255) / 256, 256>>>(cam, verts, faces);
    // One warp per (batch, face): 110208 warps -> 13776 blocks of 8 warps.
    raster_kernel<<<(BATCH * NFACE + 7) / 8, 256>>>();
    shade_kernel<<<(BATCH * IMGSZ * IMGSZ + 255) / 256, 256>>>(uv_imgs, sampler, out);
}